// round 15
// baseline (speedup 1.0000x reference)
#include <cuda_runtime.h>
#include <math.h>

#define NROWS 8192
#define NCOLS 8192
#define RB 32
#define CB 32
#define HID 100
#define DIO (RB * CB)                  // 1024
#define THREADS_RED 128
#define TILE_ROWS 64
#define STRIP_COLS 512                 // 128 thr x 4 floats
#define ST_V4 (NCOLS / 4)              // float4 row stride
#define N_STRIPS (NCOLS / STRIP_COLS)  // 16
#define TILES_PER_STRIP (NROWS / TILE_ROWS)        // 128
#define N_TILES (N_STRIPS * TILES_PER_STRIP)       // 2048
#define MAXRUNS 33
#define STREAM_CTAS (148 * 7)          // 1036: perfectly CTA-balanced on 148 SMs
#define L1_CTAS 16
#define TAIL_CTAS (L1_CTAS + 1)

// Device-global scratch (no allocations allowed). g_blk/g_h1 are accumulators
// re-zeroed after consumption; g_count/g_flag reset by the stream kernel's
// side CTA (stream-ordered before the tail each replay). g_h2/g_rcum/g_ccum
// are fully overwritten each replay.
__device__ float g_blk[DIO];
__device__ float g_h1[HID];
__device__ float g_h2[HID];
__device__ int   g_rcum[RB + 1];
__device__ int   g_ccum[CB + 1];
__device__ unsigned int g_count;
__device__ int   g_flag;

__device__ __forceinline__ int lb_count_less(const int* __restrict__ a,
                                             int n, int key) {
    int lo = 0, hi = n;
    while (lo < hi) {
        int mid = (lo + hi) >> 1;
        if (__ldg(&a[mid]) < key) lo = mid + 1; else hi = mid;
    }
    return lo;
}

// ---------------------------------------------------------------------------
// Kernel 1: segmented block-sum reduce, grid 1037 x 128.
// bid < 1036 : stream CTA. Statically owns tiles [bid*2048/1036,
//              (bid+1)*2048/1036) — 1 or 2 tiles of 64 rows x 512 cols.
//              Strip-major tile order => a CTA's tiles are ADJACENT row
//              chunks in the SAME strip (locality identical to the proven
//              128-row chunk). Per-SM load: 13-14 tiles (+-3.6%) vs the old
//              6-vs-7-CTA split (+-17% straggler).
// bid == 1036: side CTA — cumsums + tail-state reset only (off the
//              straggler path).
// Hot loop: proven run-based branch-free body, 8 front-batched float4
// streaming loads, two accumulator quads.
// ---------------------------------------------------------------------------
__global__ __launch_bounds__(THREADS_RED)
void mar_reduce_kernel(const float* __restrict__ X,
                       const int* __restrict__ row_ids,
                       const int* __restrict__ col_ids,
                       float* __restrict__ out) {
    const int tid = threadIdx.x;
    const int bid = blockIdx.x;

    if (bid == STREAM_CTAS) {
        // Side CTA: cumsums via lower_bound on sorted ids + state reset.
        if (tid <= RB) {
            int v = lb_count_less(row_ids, NROWS, tid);
            g_rcum[tid] = v;
            out[DIO + tid] = (float)v;
        } else if (tid < 2 * (RB + 1)) {
            int t = tid - (RB + 1);
            int v = lb_count_less(col_ids, NCOLS, t);
            g_ccum[t] = v;
            out[DIO + (RB + 1) + t] = (float)v;
        } else if (tid == 2 * (RB + 1)) {
            g_count = 0;
        } else if (tid == 2 * (RB + 1) + 1) {
            g_flag = 0;
        }
        return;
    }

    __shared__ float s_blk[DIO];
    __shared__ unsigned char s_rseg[TILE_ROWS];
    __shared__ short s_run_start[MAXRUNS + 1];
    __shared__ unsigned char s_run_seg[MAXRUNS];
    __shared__ int s_nrun;

    for (int i = tid; i < DIO; i += THREADS_RED) s_blk[i] = 0.0f;

    const int t0 = (int)(((long long)bid * N_TILES) / STREAM_CTAS);
    const int t1 = (int)(((long long)(bid + 1) * N_TILES) / STREAM_CTAS);

    for (int t = t0; t < t1; t++) {
        const int strip = t >> 7;                 // t / TILES_PER_STRIP
        const int r0 = (t & (TILES_PER_STRIP - 1)) * TILE_ROWS;
        const int c0 = strip * STRIP_COLS + tid * 4;

        if (tid < TILE_ROWS)
            s_rseg[tid] = (unsigned char)__ldg(&row_ids[r0 + tid]);
        const int cs0 = __ldg(&col_ids[c0 + 0]);
        const int cs1 = __ldg(&col_ids[c0 + 1]);
        const int cs2 = __ldg(&col_ids[c0 + 2]);
        const int cs3 = __ldg(&col_ids[c0 + 3]);
        __syncthreads();

        if (tid == 0) {                           // run list over 64 sorted ids
            int n = 0, prev = -1;
            for (int r = 0; r < TILE_ROWS; r++) {
                int s = s_rseg[r];
                if (s != prev) {
                    s_run_start[n] = (short)r;
                    s_run_seg[n] = (unsigned char)s;
                    n++; prev = s;
                }
            }
            s_run_start[n] = TILE_ROWS;
            s_nrun = n;
        }
        __syncthreads();

        const float4* __restrict__ p =
            (const float4*)(X + (size_t)r0 * NCOLS + c0);
        const int nrun = s_nrun;

        for (int run = 0; run < nrun; run++) {
            const int rs = s_run_start[run];
            const int re = s_run_start[run + 1];
            const int seg = s_run_seg[run];
            const float4* __restrict__ q = p + (size_t)rs * ST_V4;
            const int n = re - rs;

            float a0 = 0.f, a1 = 0.f, a2 = 0.f, a3 = 0.f;
            float b0 = 0.f, b1 = 0.f, b2 = 0.f, b3 = 0.f;
            int r = 0;
            for (; r + 8 <= n; r += 8) {
                float4 v0 = __ldcs(&q[(size_t)(r + 0) * ST_V4]);
                float4 v1 = __ldcs(&q[(size_t)(r + 1) * ST_V4]);
                float4 v2 = __ldcs(&q[(size_t)(r + 2) * ST_V4]);
                float4 v3 = __ldcs(&q[(size_t)(r + 3) * ST_V4]);
                float4 v4 = __ldcs(&q[(size_t)(r + 4) * ST_V4]);
                float4 v5 = __ldcs(&q[(size_t)(r + 5) * ST_V4]);
                float4 v6 = __ldcs(&q[(size_t)(r + 6) * ST_V4]);
                float4 v7 = __ldcs(&q[(size_t)(r + 7) * ST_V4]);
                a0 += v0.x; a1 += v0.y; a2 += v0.z; a3 += v0.w;
                b0 += v1.x; b1 += v1.y; b2 += v1.z; b3 += v1.w;
                a0 += v2.x; a1 += v2.y; a2 += v2.z; a3 += v2.w;
                b0 += v3.x; b1 += v3.y; b2 += v3.z; b3 += v3.w;
                a0 += v4.x; a1 += v4.y; a2 += v4.z; a3 += v4.w;
                b0 += v5.x; b1 += v5.y; b2 += v5.z; b3 += v5.w;
                a0 += v6.x; a1 += v6.y; a2 += v6.z; a3 += v6.w;
                b0 += v7.x; b1 += v7.y; b2 += v7.z; b3 += v7.w;
            }
            for (; r < n; r++) {
                float4 v = __ldcs(&q[(size_t)r * ST_V4]);
                a0 += v.x; a1 += v.y; a2 += v.z; a3 += v.w;
            }
            const int base = seg * CB;
            atomicAdd(&s_blk[base + cs0], a0 + b0);
            atomicAdd(&s_blk[base + cs1], a1 + b1);
            atomicAdd(&s_blk[base + cs2], a2 + b2);
            atomicAdd(&s_blk[base + cs3], a3 + b3);
        }
        __syncthreads();            // protect s_rseg/runs before next tile
    }

    // Merge only nonzero bins to global.
    for (int i = tid; i < DIO; i += THREADS_RED) {
        float v = s_blk[i];
        if (v != 0.0f) atomicAdd(&g_blk[i], v);
    }
}

// ---------------------------------------------------------------------------
// Kernel 2 (fused tail), grid 17 x 256 — R14 verbatim (best-measured):
//  CTA 16 (L2 specialist): stream W2+b1+b2 into SHARED while the L1 CTAs run
//    phase A; spin on arrival counter; compute h2 from shared; publish flag.
//  CTAs 0..15: prefetch W3 slice (25 regs) + b3 first (latency overlapped);
//    phase A: block means + W1 partials -> g_h1, arrive; spin flag;
//    phase C: pure-FMA L3 + sigmoid.
// ---------------------------------------------------------------------------
__global__ __launch_bounds__(256)
void mar_tail_kernel(const float* __restrict__ W1, const float* __restrict__ b1,
                     const float* __restrict__ W2, const float* __restrict__ b2,
                     const float* __restrict__ W3, const float* __restrict__ b3,
                     float* __restrict__ out) {
    const int tid = threadIdx.x;
    const int cta = blockIdx.x;

    if (cta == L1_CTAS) {
        __shared__ float s_w2[HID * HID];   // 40 KB
        __shared__ float s_b[2][HID];
        __shared__ float s_h1[HID];

        for (int i = tid; i < HID * HID; i += 256)
            s_w2[i] = __ldg(&W2[i]);
        if (tid < HID) {
            s_b[0][tid] = __ldg(&b1[tid]);
            s_b[1][tid] = __ldg(&b2[tid]);
        }
        __syncthreads();

        if (tid == 0) {
            while (atomicAdd(&g_count, 0u) < (unsigned)L1_CTAS) { }
        }
        __syncthreads();
        __threadfence();

        if (tid < HID) {
            s_h1[tid] = fmaxf(__ldcg(&g_h1[tid]) + s_b[0][tid], 0.0f);
            g_h1[tid] = 0.0f;               // clean for next replay
        }
        __syncthreads();

        if (tid < HID) {
            float s = s_b[1][tid];
            const float* __restrict__ w = s_w2 + tid;
#pragma unroll 20
            for (int i = 0; i < HID; i++)
                s += s_h1[i] * w[i * HID];
            g_h2[tid] = fmaxf(s, 0.0f);
        }
        __threadfence();
        __syncthreads();
        if (tid == 0) atomicExch(&g_flag, 1);
        return;
    }

    __shared__ float s_x[64];
    __shared__ float s_h2[HID];
    __shared__ float s_part[3][64];

    const int i0 = cta * 64;
    const int lane = tid & 63;
    const int part = tid >> 6;              // 0..3, 25 W3 rows each
    const int j = cta * 64 + lane;
    const int ibeg = part * 25;

    float w3r[25];
    {
        const float* __restrict__ w = W3 + (size_t)ibeg * DIO + j;
#pragma unroll 25
        for (int i = 0; i < 25; i++)
            w3r[i] = __ldg(&w[(size_t)i * DIO]);
    }
    const float b3r = (part == 0) ? __ldg(&b3[j]) : 0.0f;

    if (tid < 64) {
        int i = i0 + tid;
        int ri = i >> 5, ci = i & 31;
        float rc = (float)(g_rcum[ri + 1] - g_rcum[ri]);
        float cc = (float)(g_ccum[ci + 1] - g_ccum[ci]);
        s_x[tid] = __ldcg(&g_blk[i]) / fmaxf(rc * cc, 1.0f);
        g_blk[i] = 0.0f;                    // consumed -> clean for next replay
    }
    __syncthreads();

    {
        const int half = tid >> 7;          // 0 or 1: 32 input rows each
        const int k = tid & 127;
        if (k < HID) {
            float s = 0.0f;
            const float* __restrict__ w = W1 + (size_t)(i0 + half * 32) * HID + k;
            const float* __restrict__ xs = s_x + half * 32;
#pragma unroll 16
            for (int i = 0; i < 32; i++)
                s += xs[i] * __ldg(&w[(size_t)i * HID]);
            atomicAdd(&g_h1[k], s);
        }
    }
    __threadfence();
    __syncthreads();
    if (tid == 0) atomicAdd(&g_count, 1u);

    if (tid == 0) {
        while (atomicAdd(&g_flag, 0) == 0) { }
    }
    __syncthreads();
    __threadfence();

    if (tid < HID) s_h2[tid] = __ldcg(&g_h2[tid]);
    __syncthreads();

    float s = 0.0f;
#pragma unroll 25
    for (int i = 0; i < 25; i++)
        s += s_h2[ibeg + i] * w3r[i];

    if (part) s_part[part - 1][lane] = s;
    __syncthreads();
    if (part == 0) {
        s += b3r + s_part[0][lane] + s_part[1][lane] + s_part[2][lane];
        out[j] = 1.0f / (1.0f + __expf(-s));
    }
}

// ---------------------------------------------------------------------------
// Launch
// ---------------------------------------------------------------------------
extern "C" void kernel_launch(void* const* d_in, const int* in_sizes, int n_in,
                              void* d_out, int out_size) {
    const float* X       = (const float*)d_in[0];
    const int*   row_ids = (const int*)d_in[1];
    const int*   col_ids = (const int*)d_in[2];
    const float* W1 = (const float*)d_in[3];
    const float* b1 = (const float*)d_in[4];
    const float* W2 = (const float*)d_in[5];
    const float* b2 = (const float*)d_in[6];
    const float* W3 = (const float*)d_in[7];
    const float* b3 = (const float*)d_in[8];
    float* out = (float*)d_out;

    mar_reduce_kernel<<<STREAM_CTAS + 1, THREADS_RED>>>(X, row_ids, col_ids, out);

    mar_tail_kernel<<<TAIL_CTAS, 256>>>(W1, b1, W2, b2, W3, b3, out);
}

// round 16
// speedup vs baseline: 1.2199x; 1.2199x over previous
#include <cuda_runtime.h>
#include <math.h>

#define NROWS 8192
#define NCOLS 8192
#define RB 32
#define CB 32
#define HID 100
#define DIO (RB * CB)                  // 1024
#define ROWS_PER_CTA 128
#define THREADS_RED 128
#define STRIP_COLS (THREADS_RED * 4)   // 512 columns per CTA strip
#define ST_V4 (NCOLS / 4)              // float4 row stride
#define MAXRUNS 33
#define L1_CTAS 16                     // tail CTAs 0..15: L1 partials + L3
#define TAIL_CTAS (L1_CTAS + 1)        // tail CTA 16: dedicated L2 CTA

// Device-global scratch (no allocations allowed). g_blk/g_h1 are accumulators
// re-zeroed after consumption; g_count/g_flag are reset by the reduce kernel
// (ordered before the tail's post-sync section by cudaGridDependencySynchronize).
__device__ float g_blk[DIO];
__device__ float g_h1[HID];
__device__ float g_h2[HID];
__device__ int   g_rcum[RB + 1];
__device__ int   g_ccum[CB + 1];
__device__ unsigned int g_count;
__device__ int   g_flag;

__device__ __forceinline__ int lb_count_less(const int* __restrict__ a,
                                             int n, int key) {
    int lo = 0, hi = n;
    while (lo < hi) {
        int mid = (lo + hi) >> 1;
        if (__ldg(&a[mid]) < key) lo = mid + 1; else hi = mid;
    }
    return lo;
}

// ---------------------------------------------------------------------------
// Kernel 1: PROVEN stream config (R6/R14, 74.2-74.5 us measured 3x).
// Grid (16, 64) x 128 — blockIdx.x (strip) fastest => concurrent CTAs read
// the same 128-row band (DRAM/L2 co-locality; every other order regressed).
// Adds ONE line vs R14: an early PDL trigger so the tail kernel can launch
// and prefetch its weights while this kernel streams X.
// ---------------------------------------------------------------------------
__global__ __launch_bounds__(THREADS_RED)
void mar_reduce_kernel(const float* __restrict__ X,
                       const int* __restrict__ row_ids,
                       const int* __restrict__ col_ids,
                       float* __restrict__ out) {
    __shared__ float s_blk[DIO];
    __shared__ unsigned char s_rseg[ROWS_PER_CTA];
    __shared__ short s_run_start[MAXRUNS + 1];
    __shared__ unsigned char s_run_seg[MAXRUNS];
    __shared__ int s_nrun;

    const int tid = threadIdx.x;
    const int r0 = blockIdx.y * ROWS_PER_CTA;
    const int c0 = blockIdx.x * STRIP_COLS + tid * 4;

    for (int i = tid; i < DIO; i += THREADS_RED) s_blk[i] = 0.0f;
    if (tid < ROWS_PER_CTA)
        s_rseg[tid] = (unsigned char)row_ids[r0 + tid];

    const int cs0 = col_ids[c0 + 0];
    const int cs1 = col_ids[c0 + 1];
    const int cs2 = col_ids[c0 + 2];
    const int cs3 = col_ids[c0 + 3];
    __syncthreads();

    // Build run list (sorted ids -> typically 1-2 runs per 128-row chunk).
    if (tid == 0) {
        int n = 0, prev = -1;
        for (int r = 0; r < ROWS_PER_CTA; r++) {
            int s = s_rseg[r];
            if (s != prev) {
                s_run_start[n] = (short)r;
                s_run_seg[n] = (unsigned char)s;
                n++; prev = s;
            }
        }
        s_run_start[n] = ROWS_PER_CTA;
        s_nrun = n;
    }
    __syncthreads();

#if __CUDA_ARCH__ >= 900
    // PDL: signal launch-readiness of the dependent (tail) kernel early.
    // All 1024 CTAs are wave-1 resident -> trigger completes ~5us in,
    // letting the tail prefetch ~840 KB of weights under this stream.
    if (tid == 0) cudaTriggerProgrammaticLaunchCompletion();
#endif

    const float4* __restrict__ p = (const float4*)(X + (size_t)r0 * NCOLS + c0);
    const int nrun = s_nrun;

    for (int run = 0; run < nrun; run++) {
        const int rs = s_run_start[run];
        const int re = s_run_start[run + 1];
        const int seg = s_run_seg[run];
        const float4* __restrict__ q = p + (size_t)rs * ST_V4;
        const int n = re - rs;

        float a0 = 0.f, a1 = 0.f, a2 = 0.f, a3 = 0.f;
        float b0 = 0.f, b1 = 0.f, b2 = 0.f, b3 = 0.f;
        int r = 0;
        for (; r + 8 <= n; r += 8) {
            float4 v0 = __ldcs(&q[(size_t)(r + 0) * ST_V4]);
            float4 v1 = __ldcs(&q[(size_t)(r + 1) * ST_V4]);
            float4 v2 = __ldcs(&q[(size_t)(r + 2) * ST_V4]);
            float4 v3 = __ldcs(&q[(size_t)(r + 3) * ST_V4]);
            float4 v4 = __ldcs(&q[(size_t)(r + 4) * ST_V4]);
            float4 v5 = __ldcs(&q[(size_t)(r + 5) * ST_V4]);
            float4 v6 = __ldcs(&q[(size_t)(r + 6) * ST_V4]);
            float4 v7 = __ldcs(&q[(size_t)(r + 7) * ST_V4]);
            a0 += v0.x; a1 += v0.y; a2 += v0.z; a3 += v0.w;
            b0 += v1.x; b1 += v1.y; b2 += v1.z; b3 += v1.w;
            a0 += v2.x; a1 += v2.y; a2 += v2.z; a3 += v2.w;
            b0 += v3.x; b1 += v3.y; b2 += v3.z; b3 += v3.w;
            a0 += v4.x; a1 += v4.y; a2 += v4.z; a3 += v4.w;
            b0 += v5.x; b1 += v5.y; b2 += v5.z; b3 += v5.w;
            a0 += v6.x; a1 += v6.y; a2 += v6.z; a3 += v6.w;
            b0 += v7.x; b1 += v7.y; b2 += v7.z; b3 += v7.w;
        }
        for (; r < n; r++) {
            float4 v = __ldcs(&q[(size_t)r * ST_V4]);
            a0 += v.x; a1 += v.y; a2 += v.z; a3 += v.w;
        }
        const int base = seg * CB;
        atomicAdd(&s_blk[base + cs0], a0 + b0);
        atomicAdd(&s_blk[base + cs1], a1 + b1);
        atomicAdd(&s_blk[base + cs2], a2 + b2);
        atomicAdd(&s_blk[base + cs3], a3 + b3);
    }
    __syncthreads();

    for (int i = tid; i < DIO; i += THREADS_RED) {
        float v = s_blk[i];
        if (v != 0.0f) atomicAdd(&g_blk[i], v);
    }

    // Side task (one CTA): cumsums + reset tail sync state for this replay.
    if (blockIdx.x == 0 && blockIdx.y == 0) {
        if (tid <= RB) {
            int v = lb_count_less(row_ids, NROWS, tid);
            g_rcum[tid] = v;
            out[DIO + tid] = (float)v;
        } else if (tid < 2 * (RB + 1)) {
            int t = tid - (RB + 1);
            int v = lb_count_less(col_ids, NCOLS, t);
            g_ccum[t] = v;
            out[DIO + (RB + 1) + t] = (float)v;
        } else if (tid == 2 * (RB + 1)) {
            g_count = 0;
        } else if (tid == 2 * (RB + 1) + 1) {
            g_flag = 0;
        }
    }
}

// ---------------------------------------------------------------------------
// Kernel 2 (fused tail), grid 17 x 256, launched with PDL
// (programmaticStreamSerialization). PRE-SYNC: every CTA issues ALL its
// weight traffic (runs concurrently with the reduce stream). POST-SYNC
// (cudaGridDependencySynchronize = reduce complete + memory visible): only
// L2-hit g_blk reads + FMAs + two tiny CTA handshakes remain (~2-3 us).
//  CTA 16: W2 -> shared (float4) + b1/b2 pre-sync; spin g_count; h2; flag.
//  CTAs 0..15: W3 slice (25 regs) + W1 slice (32 regs) + b3 pre-sync;
//    post-sync: block means, W1 partials from regs -> g_h1, arrive; spin
//    flag; pure-FMA L3 + sigmoid.
// ---------------------------------------------------------------------------
__global__ __launch_bounds__(256)
void mar_tail_kernel(const float* __restrict__ W1, const float* __restrict__ b1,
                     const float* __restrict__ W2, const float* __restrict__ b2,
                     const float* __restrict__ W3, const float* __restrict__ b3,
                     float* __restrict__ out) {
    const int tid = threadIdx.x;
    const int cta = blockIdx.x;

    if (cta == L1_CTAS) {
        // ================= L2 specialist CTA =================
        __shared__ float s_w2[HID * HID];   // 40 KB
        __shared__ float s_b[2][HID];
        __shared__ float s_h1[HID];

        // --- PRE-SYNC: stream W2 into shared (10 independent float4/thread)
        {
            const float4* __restrict__ w2v = (const float4*)W2;
            float4* __restrict__ dst = (float4*)s_w2;
#pragma unroll 10
            for (int i = tid; i < (HID * HID) / 4; i += 256)
                dst[i] = __ldg(&w2v[i]);
        }
        if (tid < HID) {
            s_b[0][tid] = __ldg(&b1[tid]);
            s_b[1][tid] = __ldg(&b2[tid]);
        }

#if __CUDA_ARCH__ >= 900
        cudaGridDependencySynchronize();    // reduce complete + visible
#endif
        __syncthreads();

        if (tid == 0) {
            while (atomicAdd(&g_count, 0u) < (unsigned)L1_CTAS) { }
        }
        __syncthreads();
        __threadfence();

        if (tid < HID) {
            s_h1[tid] = fmaxf(__ldcg(&g_h1[tid]) + s_b[0][tid], 0.0f);
            g_h1[tid] = 0.0f;               // clean for next replay
        }
        __syncthreads();

        if (tid < HID) {
            float s = s_b[1][tid];
            const float* __restrict__ w = s_w2 + tid;
#pragma unroll 20
            for (int i = 0; i < HID; i++)
                s += s_h1[i] * w[i * HID];
            g_h2[tid] = fmaxf(s, 0.0f);
        }
        __threadfence();
        __syncthreads();
        if (tid == 0) atomicExch(&g_flag, 1);
        return;
    }

    // ================= L1 + L3 CTAs =================
    __shared__ float s_x[64];
    __shared__ float s_h2[HID];
    __shared__ float s_part[3][64];

    const int i0 = cta * 64;
    const int lane = tid & 63;
    const int part = tid >> 6;              // 0..3, 25 W3 rows each
    const int j = cta * 64 + lane;
    const int ibeg = part * 25;
    const int half = tid >> 7;              // 0 or 1: 32 W1 input rows each
    const int k = tid & 127;                // h1 lane (active < HID)

    // --- PRE-SYNC: all weight loads issued while the reduce streams ---
    float w3r[25];
    {
        const float* __restrict__ w = W3 + (size_t)ibeg * DIO + j;
#pragma unroll 25
        for (int i = 0; i < 25; i++)
            w3r[i] = __ldg(&w[(size_t)i * DIO]);
    }
    const float b3r = (part == 0) ? __ldg(&b3[j]) : 0.0f;

    float w1r[32];
    if (k < HID) {
        const float* __restrict__ w = W1 + (size_t)(i0 + half * 32) * HID + k;
#pragma unroll 32
        for (int i = 0; i < 32; i++)
            w1r[i] = __ldg(&w[(size_t)i * HID]);
    }

#if __CUDA_ARCH__ >= 900
    cudaGridDependencySynchronize();        // reduce complete + visible
#endif

    // ---- Phase A: block means (g_blk is L2-hot from the reduce atomics) ----
    if (tid < 64) {
        int i = i0 + tid;
        int ri = i >> 5, ci = i & 31;
        float rc = (float)(g_rcum[ri + 1] - g_rcum[ri]);
        float cc = (float)(g_ccum[ci + 1] - g_ccum[ci]);
        s_x[tid] = __ldcg(&g_blk[i]) / fmaxf(rc * cc, 1.0f);
        g_blk[i] = 0.0f;                    // consumed -> clean for next replay
    }
    __syncthreads();

    // ---- Phase A: W1 partials — pure FMA from prefetched registers ----
    if (k < HID) {
        float s = 0.0f;
        const float* __restrict__ xs = s_x + half * 32;
#pragma unroll 32
        for (int i = 0; i < 32; i++)
            s += xs[i] * w1r[i];
        atomicAdd(&g_h1[k], s);
    }
    __threadfence();                        // h1 partials visible before arrive
    __syncthreads();
    if (tid == 0) atomicAdd(&g_count, 1u);

    // ---- Wait for h2 (17 CTAs co-resident alongside the drained reduce) ----
    if (tid == 0) {
        while (atomicAdd(&g_flag, 0) == 0) { }
    }
    __syncthreads();
    __threadfence();

    if (tid < HID) s_h2[tid] = __ldcg(&g_h2[tid]);
    __syncthreads();

    // ---- Phase C: pure-FMA L3 + sigmoid ----
    float s = 0.0f;
#pragma unroll 25
    for (int i = 0; i < 25; i++)
        s += s_h2[ibeg + i] * w3r[i];

    if (part) s_part[part - 1][lane] = s;
    __syncthreads();
    if (part == 0) {
        s += b3r + s_part[0][lane] + s_part[1][lane] + s_part[2][lane];
        out[j] = 1.0f / (1.0f + __expf(-s));
    }
}

// ---------------------------------------------------------------------------
// Launch: reduce normally; tail via cudaLaunchKernelEx with PDL so its
// weight-prefetch preamble overlaps the reduce stream.
// ---------------------------------------------------------------------------
extern "C" void kernel_launch(void* const* d_in, const int* in_sizes, int n_in,
                              void* d_out, int out_size) {
    const float* X       = (const float*)d_in[0];
    const int*   row_ids = (const int*)d_in[1];
    const int*   col_ids = (const int*)d_in[2];
    const float* W1 = (const float*)d_in[3];
    const float* b1 = (const float*)d_in[4];
    const float* W2 = (const float*)d_in[5];
    const float* b2 = (const float*)d_in[6];
    const float* W3 = (const float*)d_in[7];
    const float* b3 = (const float*)d_in[8];
    float* out = (float*)d_out;

    dim3 grid(NCOLS / STRIP_COLS, NROWS / ROWS_PER_CTA);   // (16, 64)
    mar_reduce_kernel<<<grid, THREADS_RED>>>(X, row_ids, col_ids, out);

    cudaLaunchConfig_t cfg = {};
    cfg.gridDim = dim3(TAIL_CTAS, 1, 1);
    cfg.blockDim = dim3(256, 1, 1);
    cfg.dynamicSmemBytes = 0;
    cfg.stream = 0;                        // same (legacy) stream as <<<>>>
    cudaLaunchAttribute attrs[1];
    attrs[0].id = cudaLaunchAttributeProgrammaticStreamSerialization;
    attrs[0].val.programmaticStreamSerializationAllowed = 1;
    cfg.attrs = attrs;
    cfg.numAttrs = 1;
    cudaLaunchKernelEx(&cfg, mar_tail_kernel, W1, b1, W2, b2, W3, b3, out);
}

// round 17
// speedup vs baseline: 1.2589x; 1.0319x over previous
#include <cuda_runtime.h>
#include <math.h>

#define NROWS 8192
#define NCOLS 8192
#define RB 32
#define CB 32
#define HID 100
#define DIO (RB * CB)                  // 1024
#define ROWS_PER_CTA 128
#define THREADS_RED 128
#define STRIP_COLS (THREADS_RED * 4)   // 512 columns per CTA strip
#define ST_V4 (NCOLS / 4)              // float4 row stride
#define MAXRUNS 33
#define L1_CTAS 16                     // tail CTAs 0..15: L1 partials + L3
#define TAIL_CTAS (L1_CTAS + 1)        // tail CTA 16: dedicated L2 CTA

// Device-global scratch (no allocations allowed). g_blk/g_h1 are accumulators
// re-zeroed after consumption; g_count/g_flag are reset by the reduce kernel
// (ordered before the tail's post-sync section by cudaGridDependencySynchronize).
__device__ float g_blk[DIO];
__device__ float g_h1[HID];
__device__ float g_h2[HID];
__device__ int   g_rcum[RB + 1];
__device__ int   g_ccum[CB + 1];
__device__ unsigned int g_count;
__device__ int   g_flag;

__device__ __forceinline__ int lb_count_less(const int* __restrict__ a,
                                             int n, int key) {
    int lo = 0, hi = n;
    while (lo < hi) {
        int mid = (lo + hi) >> 1;
        if (__ldg(&a[mid]) < key) lo = mid + 1; else hi = mid;
    }
    return lo;
}

// ---------------------------------------------------------------------------
// Kernel 1: segmented block-sum reduce. Grid (16, 64) x 128 (proven layout —
// bx fastest => concurrent CTAs share a row band; every other order lost).
// NEW vs R16: the hot loop is SOFTWARE-PIPELINED (4-float4 double buffer,
// unroll-2 rotate). The old 8-load/32-FADD batch left DRAM idle 55% of
// cycles (in-order issue: next batch's loads blocked behind the consume).
// Now batch B's loads are in flight WHILE batch A is consumed -> loads in
// flight near-continuously per warp. ~58 regs, still 7 CTAs/SM single-wave.
// ---------------------------------------------------------------------------
__global__ __launch_bounds__(THREADS_RED)
void mar_reduce_kernel(const float* __restrict__ X,
                       const int* __restrict__ row_ids,
                       const int* __restrict__ col_ids,
                       float* __restrict__ out) {
    __shared__ float s_blk[DIO];
    __shared__ unsigned char s_rseg[ROWS_PER_CTA];
    __shared__ short s_run_start[MAXRUNS + 1];
    __shared__ unsigned char s_run_seg[MAXRUNS];
    __shared__ int s_nrun;

    const int tid = threadIdx.x;
    const int r0 = blockIdx.y * ROWS_PER_CTA;
    const int c0 = blockIdx.x * STRIP_COLS + tid * 4;

    for (int i = tid; i < DIO; i += THREADS_RED) s_blk[i] = 0.0f;
    if (tid < ROWS_PER_CTA)
        s_rseg[tid] = (unsigned char)row_ids[r0 + tid];

    const int cs0 = col_ids[c0 + 0];
    const int cs1 = col_ids[c0 + 1];
    const int cs2 = col_ids[c0 + 2];
    const int cs3 = col_ids[c0 + 3];
    __syncthreads();

    // Build run list (sorted ids -> typically 1-2 runs per 128-row chunk).
    if (tid == 0) {
        int n = 0, prev = -1;
        for (int r = 0; r < ROWS_PER_CTA; r++) {
            int s = s_rseg[r];
            if (s != prev) {
                s_run_start[n] = (short)r;
                s_run_seg[n] = (unsigned char)s;
                n++; prev = s;
            }
        }
        s_run_start[n] = ROWS_PER_CTA;
        s_nrun = n;
    }
    __syncthreads();

#if __CUDA_ARCH__ >= 900
    // PDL: let the tail kernel launch + prefetch weights under this stream.
    if (tid == 0) cudaTriggerProgrammaticLaunchCompletion();
#endif

    const float4* __restrict__ p = (const float4*)(X + (size_t)r0 * NCOLS + c0);
    const int nrun = s_nrun;

    for (int run = 0; run < nrun; run++) {
        const int rs = s_run_start[run];
        const int re = s_run_start[run + 1];
        const int seg = s_run_seg[run];
        const float4* __restrict__ q = p + (size_t)rs * ST_V4;
        const int n = re - rs;

        float a0 = 0.f, a1 = 0.f, a2 = 0.f, a3 = 0.f;
        float b0 = 0.f, b1 = 0.f, b2 = 0.f, b3 = 0.f;
        int r = 0;

        if (n >= 12) {
            // Prologue: prime buffer A with rows 0..3.
            float4 A0 = __ldcs(&q[(size_t)0 * ST_V4]);
            float4 A1 = __ldcs(&q[(size_t)1 * ST_V4]);
            float4 A2 = __ldcs(&q[(size_t)2 * ST_V4]);
            float4 A3 = __ldcs(&q[(size_t)3 * ST_V4]);
            // Steady state: loads of one buffer in flight while the other
            // is consumed; unroll-2 so the A<-B rotate is register renaming.
            for (; r + 12 <= n; r += 8) {
                float4 B0 = __ldcs(&q[(size_t)(r + 4) * ST_V4]);
                float4 B1 = __ldcs(&q[(size_t)(r + 5) * ST_V4]);
                float4 B2 = __ldcs(&q[(size_t)(r + 6) * ST_V4]);
                float4 B3 = __ldcs(&q[(size_t)(r + 7) * ST_V4]);
                a0 += A0.x; a1 += A0.y; a2 += A0.z; a3 += A0.w;
                b0 += A1.x; b1 += A1.y; b2 += A1.z; b3 += A1.w;
                a0 += A2.x; a1 += A2.y; a2 += A2.z; a3 += A2.w;
                b0 += A3.x; b1 += A3.y; b2 += A3.z; b3 += A3.w;
                A0 = __ldcs(&q[(size_t)(r + 8) * ST_V4]);
                A1 = __ldcs(&q[(size_t)(r + 9) * ST_V4]);
                A2 = __ldcs(&q[(size_t)(r + 10) * ST_V4]);
                A3 = __ldcs(&q[(size_t)(r + 11) * ST_V4]);
                a0 += B0.x; a1 += B0.y; a2 += B0.z; a3 += B0.w;
                b0 += B1.x; b1 += B1.y; b2 += B1.z; b3 += B1.w;
                a0 += B2.x; a1 += B2.y; a2 += B2.z; a3 += B2.w;
                b0 += B3.x; b1 += B3.y; b2 += B3.z; b3 += B3.w;
            }
            // Epilogue: A holds rows r..r+3 (loaded by the last iteration).
            a0 += A0.x; a1 += A0.y; a2 += A0.z; a3 += A0.w;
            b0 += A1.x; b1 += A1.y; b2 += A1.z; b3 += A1.w;
            a0 += A2.x; a1 += A2.y; a2 += A2.z; a3 += A2.w;
            b0 += A3.x; b1 += A3.y; b2 += A3.z; b3 += A3.w;
            r += 4;
        }
        for (; r < n; r++) {
            float4 v = __ldcs(&q[(size_t)r * ST_V4]);
            a0 += v.x; a1 += v.y; a2 += v.z; a3 += v.w;
        }
        const int base = seg * CB;
        atomicAdd(&s_blk[base + cs0], a0 + b0);
        atomicAdd(&s_blk[base + cs1], a1 + b1);
        atomicAdd(&s_blk[base + cs2], a2 + b2);
        atomicAdd(&s_blk[base + cs3], a3 + b3);
    }
    __syncthreads();

    for (int i = tid; i < DIO; i += THREADS_RED) {
        float v = s_blk[i];
        if (v != 0.0f) atomicAdd(&g_blk[i], v);
    }

    // Side task (one CTA): cumsums + reset tail sync state for this replay.
    if (blockIdx.x == 0 && blockIdx.y == 0) {
        if (tid <= RB) {
            int v = lb_count_less(row_ids, NROWS, tid);
            g_rcum[tid] = v;
            out[DIO + tid] = (float)v;
        } else if (tid < 2 * (RB + 1)) {
            int t = tid - (RB + 1);
            int v = lb_count_less(col_ids, NCOLS, t);
            g_ccum[t] = v;
            out[DIO + (RB + 1) + t] = (float)v;
        } else if (tid == 2 * (RB + 1)) {
            g_count = 0;
        } else if (tid == 2 * (RB + 1) + 1) {
            g_flag = 0;
        }
    }
}

// ---------------------------------------------------------------------------
// Kernel 2 (fused tail), grid 17 x 256, PDL-launched — R16 verbatim.
//  CTA 16: W2 -> shared (float4) + b1/b2 pre-sync; spin g_count; h2; flag.
//  CTAs 0..15: W3 slice (25 regs) + W1 slice (32 regs) + b3 pre-sync;
//    post-sync: block means, W1 partials from regs -> g_h1, arrive; spin
//    flag; pure-FMA L3 + sigmoid.
// ---------------------------------------------------------------------------
__global__ __launch_bounds__(256)
void mar_tail_kernel(const float* __restrict__ W1, const float* __restrict__ b1,
                     const float* __restrict__ W2, const float* __restrict__ b2,
                     const float* __restrict__ W3, const float* __restrict__ b3,
                     float* __restrict__ out) {
    const int tid = threadIdx.x;
    const int cta = blockIdx.x;

    if (cta == L1_CTAS) {
        __shared__ float s_w2[HID * HID];   // 40 KB
        __shared__ float s_b[2][HID];
        __shared__ float s_h1[HID];

        {
            const float4* __restrict__ w2v = (const float4*)W2;
            float4* __restrict__ dst = (float4*)s_w2;
#pragma unroll 10
            for (int i = tid; i < (HID * HID) / 4; i += 256)
                dst[i] = __ldg(&w2v[i]);
        }
        if (tid < HID) {
            s_b[0][tid] = __ldg(&b1[tid]);
            s_b[1][tid] = __ldg(&b2[tid]);
        }

#if __CUDA_ARCH__ >= 900
        cudaGridDependencySynchronize();    // reduce complete + visible
#endif
        __syncthreads();

        if (tid == 0) {
            while (atomicAdd(&g_count, 0u) < (unsigned)L1_CTAS) { }
        }
        __syncthreads();
        __threadfence();

        if (tid < HID) {
            s_h1[tid] = fmaxf(__ldcg(&g_h1[tid]) + s_b[0][tid], 0.0f);
            g_h1[tid] = 0.0f;               // clean for next replay
        }
        __syncthreads();

        if (tid < HID) {
            float s = s_b[1][tid];
            const float* __restrict__ w = s_w2 + tid;
#pragma unroll 20
            for (int i = 0; i < HID; i++)
                s += s_h1[i] * w[i * HID];
            g_h2[tid] = fmaxf(s, 0.0f);
        }
        __threadfence();
        __syncthreads();
        if (tid == 0) atomicExch(&g_flag, 1);
        return;
    }

    __shared__ float s_x[64];
    __shared__ float s_h2[HID];
    __shared__ float s_part[3][64];

    const int i0 = cta * 64;
    const int lane = tid & 63;
    const int part = tid >> 6;              // 0..3, 25 W3 rows each
    const int j = cta * 64 + lane;
    const int ibeg = part * 25;
    const int half = tid >> 7;              // 0 or 1: 32 W1 input rows each
    const int k = tid & 127;                // h1 lane (active < HID)

    float w3r[25];
    {
        const float* __restrict__ w = W3 + (size_t)ibeg * DIO + j;
#pragma unroll 25
        for (int i = 0; i < 25; i++)
            w3r[i] = __ldg(&w[(size_t)i * DIO]);
    }
    const float b3r = (part == 0) ? __ldg(&b3[j]) : 0.0f;

    float w1r[32];
    if (k < HID) {
        const float* __restrict__ w = W1 + (size_t)(i0 + half * 32) * HID + k;
#pragma unroll 32
        for (int i = 0; i < 32; i++)
            w1r[i] = __ldg(&w[(size_t)i * HID]);
    }

#if __CUDA_ARCH__ >= 900
    cudaGridDependencySynchronize();        // reduce complete + visible
#endif

    if (tid < 64) {
        int i = i0 + tid;
        int ri = i >> 5, ci = i & 31;
        float rc = (float)(g_rcum[ri + 1] - g_rcum[ri]);
        float cc = (float)(g_ccum[ci + 1] - g_ccum[ci]);
        s_x[tid] = __ldcg(&g_blk[i]) / fmaxf(rc * cc, 1.0f);
        g_blk[i] = 0.0f;                    // consumed -> clean for next replay
    }
    __syncthreads();

    if (k < HID) {
        float s = 0.0f;
        const float* __restrict__ xs = s_x + half * 32;
#pragma unroll 32
        for (int i = 0; i < 32; i++)
            s += xs[i] * w1r[i];
        atomicAdd(&g_h1[k], s);
    }
    __threadfence();
    __syncthreads();
    if (tid == 0) atomicAdd(&g_count, 1u);

    if (tid == 0) {
        while (atomicAdd(&g_flag, 0) == 0) { }
    }
    __syncthreads();
    __threadfence();

    if (tid < HID) s_h2[tid] = __ldcg(&g_h2[tid]);
    __syncthreads();

    float s = 0.0f;
#pragma unroll 25
    for (int i = 0; i < 25; i++)
        s += s_h2[ibeg + i] * w3r[i];

    if (part) s_part[part - 1][lane] = s;
    __syncthreads();
    if (part == 0) {
        s += b3r + s_part[0][lane] + s_part[1][lane] + s_part[2][lane];
        out[j] = 1.0f / (1.0f + __expf(-s));
    }
}

// ---------------------------------------------------------------------------
// Launch: reduce normally; tail via PDL so its weight prefetch overlaps.
// ---------------------------------------------------------------------------
extern "C" void kernel_launch(void* const* d_in, const int* in_sizes, int n_in,
                              void* d_out, int out_size) {
    const float* X       = (const float*)d_in[0];
    const int*   row_ids = (const int*)d_in[1];
    const int*   col_ids = (const int*)d_in[2];
    const float* W1 = (const float*)d_in[3];
    const float* b1 = (const float*)d_in[4];
    const float* W2 = (const float*)d_in[5];
    const float* b2 = (const float*)d_in[6];
    const float* W3 = (const float*)d_in[7];
    const float* b3 = (const float*)d_in[8];
    float* out = (float*)d_out;

    dim3 grid(NCOLS / STRIP_COLS, NROWS / ROWS_PER_CTA);   // (16, 64)
    mar_reduce_kernel<<<grid, THREADS_RED>>>(X, row_ids, col_ids, out);

    cudaLaunchConfig_t cfg = {};
    cfg.gridDim = dim3(TAIL_CTAS, 1, 1);
    cfg.blockDim = dim3(256, 1, 1);
    cfg.dynamicSmemBytes = 0;
    cfg.stream = 0;                        // same (legacy) stream as <<<>>>
    cudaLaunchAttribute attrs[1];
    attrs[0].id = cudaLaunchAttributeProgrammaticStreamSerialization;
    attrs[0].val.programmaticStreamSerializationAllowed = 1;
    cfg.attrs = attrs;
    cfg.numAttrs = 1;
    cudaLaunchKernelEx(&cfg, mar_tail_kernel, W1, b1, W2, b2, W3, b3, out);
}